// round 1
// baseline (speedup 1.0000x reference)
#include <cuda_runtime.h>
#include <float.h>
#include <math.h>

#define NB 16
#define NP 1024
#define NC 91
#define MAX_DET 100
#define SCORE_THRESH 0.05f
#define NMS_THRESH 0.5f
#define BBOX_CLIP 4.135166556742356f  /* log(1000/16) */

// ---------------- scratch (no allocations allowed) ----------------
__device__ float  g_scores[NB * NP];
__device__ int    g_labels[NB * NP];
__device__ float4 g_boxes[NB * NP];
__device__ int    g_valid[NB * NP];

// ---------------- Kernel A: softmax-max/argmax + decode + clip ----------------
// One warp per proposal. Lanes cover classes {lane, lane+32, lane+64}.
__global__ void score_decode_kernel(const float* __restrict__ logits,
                                    const float* __restrict__ deltas,
                                    const float* __restrict__ props,
                                    const int*   __restrict__ imsz) {
    int gw   = (blockIdx.x * blockDim.x + threadIdx.x) >> 5;
    int lane = threadIdx.x & 31;
    if (gw >= NB * NP) return;

    const float* row = logits + (size_t)gw * NC;
    float l0 = row[lane];
    float l1 = row[lane + 32];
    bool  has2 = (lane < NC - 64);           // lane < 27
    float l2 = has2 ? row[lane + 64] : -FLT_MAX;

    // local argmax with first-index tie break
    float bv = l0; int bi = lane;
    if (l1 > bv) { bv = l1; bi = lane + 32; }
    if (l2 > bv) { bv = l2; bi = lane + 64; }
    // warp reduce (max value, min index on tie)
    #pragma unroll
    for (int o = 16; o; o >>= 1) {
        float ov = __shfl_down_sync(0xffffffffu, bv, o);
        int   oi = __shfl_down_sync(0xffffffffu, bi, o);
        if (ov > bv || (ov == bv && oi < bi)) { bv = ov; bi = oi; }
    }
    bv = __shfl_sync(0xffffffffu, bv, 0);
    bi = __shfl_sync(0xffffffffu, bi, 0);

    float s = expf(l0 - bv) + expf(l1 - bv) + (has2 ? expf(l2 - bv) : 0.0f);
    #pragma unroll
    for (int o = 16; o; o >>= 1) s += __shfl_down_sync(0xffffffffu, s, o);

    if (lane == 0) {
        float score = 1.0f / s;
        int label = bi;
        int b = gw / NP;
        int valid = (label > 0) && (score > SCORE_THRESH);

        const float* p = props + (size_t)gw * 4;
        float x1 = p[0], y1 = p[1], x2 = p[2], y2 = p[3];
        float w = x2 - x1, h = y2 - y1;
        float cx = x1 + 0.5f * w, cy = y1 + 0.5f * h;

        const float* dd = deltas + (size_t)gw * (NC * 4) + 4 * label;
        float dx = dd[0], dy = dd[1];
        float dw = fminf(dd[2], BBOX_CLIP), dh = fminf(dd[3], BBOX_CLIP);
        float pcx = dx * w + cx, pcy = dy * h + cy;
        float pw = expf(dw) * w, ph = expf(dh) * h;
        float bx1 = pcx - 0.5f * pw, by1 = pcy - 0.5f * ph;
        float bx2 = pcx + 0.5f * pw, by2 = pcy + 0.5f * ph;

        float hb = (float)imsz[b * 2 + 0];
        float wb = (float)imsz[b * 2 + 1];
        bx1 = fminf(fmaxf(bx1, 0.0f), wb);
        by1 = fminf(fmaxf(by1, 0.0f), hb);
        bx2 = fminf(fmaxf(bx2, 0.0f), wb);
        by2 = fminf(fmaxf(by2, 0.0f), hb);

        g_boxes[gw]  = make_float4(bx1, by1, bx2, by2);
        g_scores[gw] = score;
        g_labels[gw] = label;
        g_valid[gw]  = valid;
    }
}

// ---------------- Kernel B: per-image sort + per-class NMS + top-100 ----------------
// One CTA (1024 threads) per image.
__global__ __launch_bounds__(1024) void nms_kernel(float* __restrict__ out) {
    const int b = blockIdx.x;
    const int t = threadIdx.x;

    __shared__ unsigned long long s_key[NP];   // 8 KB
    __shared__ float4 s_obox[NP];              // 16 KB (offset boxes, sorted order)
    __shared__ int    s_kept[NP];              // 4 KB
    __shared__ float  s_red[NP];               // 4 KB
    __shared__ float  s_K;

    const int g = b * NP + t;
    float  score = g_scores[g];
    int    label = g_labels[g];
    int    valid = g_valid[g];
    float4 bx    = g_boxes[g];

    // max_coord over valid boxes (invalid contribute 0, like the reference)
    float mc = valid ? fmaxf(fmaxf(bx.x, bx.y), fmaxf(bx.z, bx.w)) : 0.0f;
    s_red[t] = mc;
    __syncthreads();
    #pragma unroll
    for (int o = 512; o; o >>= 1) {
        if (t < o) s_red[t] = fmaxf(s_red[t], s_red[t + o]);
        __syncthreads();
    }
    if (t == 0) s_K = s_red[0] + 1.0f;

    // key: [label:7][~score_bits:32][idx:10]  (ascending sort = label asc, score desc, idx asc)
    unsigned int ds = ~__float_as_uint(score);   // scores > 0, monotone in uint bits
    unsigned long long k = valid
        ? (((unsigned long long)label << 42) |
           ((unsigned long long)ds << 10) |
           (unsigned long long)(unsigned)t)
        : ~0ULL;
    s_key[t] = k;
    __syncthreads();

    // bitonic sort ascending, 1024 keys
    for (int kk = 2; kk <= NP; kk <<= 1) {
        for (int j = kk >> 1; j > 0; j >>= 1) {
            int ixj = t ^ j;
            if (ixj > t) {
                unsigned long long a = s_key[t], c = s_key[ixj];
                bool up = ((t & kk) == 0);
                if ((a > c) == up) { s_key[t] = c; s_key[ixj] = a; }
            }
            __syncthreads();
        }
    }

    // offset boxes in sorted order + kept init
    {
        unsigned long long kt = s_key[t];
        if (kt != ~0ULL) {
            int oi = (int)(kt & 1023ULL);
            int lb = (int)(kt >> 42);
            float off = (float)lb * s_K;         // matches labels*(max_coord+1.0)
            float4 v = g_boxes[b * NP + oi];
            s_obox[t] = make_float4(v.x + off, v.y + off, v.z + off, v.w + off);
            s_kept[t] = 1;
        } else {
            s_kept[t] = 0;
        }
    }
    __syncthreads();

    // per-class greedy NMS, one warp per class (classes 1..90)
    {
        int warp = t >> 5, lane = t & 31;
        for (int c = 1 + warp; c <= 90; c += 32) {
            int lo = 0, hi = 0;
            if (lane == 0) {
                int l = 0, r = NP;
                while (l < r) { int m = (l + r) >> 1; if ((int)(s_key[m] >> 42) < c) l = m + 1; else r = m; }
                lo = l;
                r = NP;
                while (l < r) { int m = (l + r) >> 1; if ((int)(s_key[m] >> 42) < c + 1) l = m + 1; else r = m; }
                hi = l;
            }
            lo = __shfl_sync(0xffffffffu, lo, 0);
            hi = __shfl_sync(0xffffffffu, hi, 0);
            for (int a = lo; a < hi - 1; ++a) {
                if (s_kept[a]) {
                    float4 A = s_obox[a];
                    float areaA = (A.z - A.x) * (A.w - A.y);
                    for (int bb = a + 1 + lane; bb < hi; bb += 32) {
                        if (s_kept[bb]) {
                            float4 Bx = s_obox[bb];
                            float areaB = (Bx.z - Bx.x) * (Bx.w - Bx.y);
                            float ltx = fmaxf(A.x, Bx.x), lty = fmaxf(A.y, Bx.y);
                            float rbx = fminf(A.z, Bx.z), rby = fminf(A.w, Bx.w);
                            float wx = fmaxf(rbx - ltx, 0.0f), wy = fmaxf(rby - lty, 0.0f);
                            float inter = wx * wy;
                            float uni = areaA + areaB - inter;
                            float iou = inter / (uni + 1e-9f);
                            if (iou > NMS_THRESH) s_kept[bb] = 0;
                        }
                    }
                }
                __syncwarp();
            }
        }
    }
    __syncthreads();

    // second key: kept entries by (score desc, idx asc); others to the end
    unsigned long long k2 = (s_kept[t] && s_key[t] != ~0ULL)
        ? (s_key[t] & ((1ULL << 42) - 1ULL))
        : ~0ULL;
    __syncthreads();
    s_key[t] = k2;
    __syncthreads();

    for (int kk = 2; kk <= NP; kk <<= 1) {
        for (int j = kk >> 1; j > 0; j >>= 1) {
            int ixj = t ^ j;
            if (ixj > t) {
                unsigned long long a = s_key[t], c = s_key[ixj];
                bool up = ((t & kk) == 0);
                if ((a > c) == up) { s_key[t] = c; s_key[ixj] = a; }
            }
            __syncthreads();
        }
    }

    // output: boxes [NB,100,4] | scores [NB,100] | labels [NB,100]  (all f32)
    if (t < MAX_DET) {
        float* boxes_out  = out;
        float* scores_out = out + NB * MAX_DET * 4;
        float* labels_out = out + NB * MAX_DET * 5;
        unsigned long long kt = s_key[t];
        int base = b * MAX_DET + t;
        if (kt != ~0ULL) {
            int oi = (int)(kt & 1023ULL);
            float4 v = g_boxes[b * NP + oi];
            boxes_out[base * 4 + 0] = v.x;
            boxes_out[base * 4 + 1] = v.y;
            boxes_out[base * 4 + 2] = v.z;
            boxes_out[base * 4 + 3] = v.w;
            scores_out[base] = g_scores[b * NP + oi];
            labels_out[base] = (float)g_labels[b * NP + oi];
        } else {
            boxes_out[base * 4 + 0] = 0.0f;
            boxes_out[base * 4 + 1] = 0.0f;
            boxes_out[base * 4 + 2] = 0.0f;
            boxes_out[base * 4 + 3] = 0.0f;
            scores_out[base] = 0.0f;
            labels_out[base] = -1.0f;
        }
    }
}

// ---------------- launch ----------------
extern "C" void kernel_launch(void* const* d_in, const int* in_sizes, int n_in,
                              void* d_out, int out_size) {
    const float* class_logits  = (const float*)d_in[0];
    const float* bbox_deltas   = (const float*)d_in[1];
    const float* roi_proposals = (const float*)d_in[2];
    const int*   image_sizes   = (const int*)d_in[3];
    float* out = (float*)d_out;

    // Kernel A: 16384 warps, 8 warps/block
    int total_warps = NB * NP;
    int threads = 256;
    int blocks = (total_warps * 32 + threads - 1) / threads;
    score_decode_kernel<<<blocks, threads>>>(class_logits, bbox_deltas,
                                             roi_proposals, image_sizes);

    // Kernel B: one CTA per image
    nms_kernel<<<NB, 1024>>>(out);
}

// round 2
// speedup vs baseline: 1.0942x; 1.0942x over previous
#include <cuda_runtime.h>
#include <float.h>
#include <math.h>

#define NB 16
#define NP 1024
#define NC 91
#define MAX_DET 100
#define SCORE_THRESH 0.05f
#define NMS_THRESH 0.5f
#define BBOX_CLIP 4.135166556742356f  /* log(1000/16) */

// ---------------- scratch (no allocations allowed) ----------------
__device__ float  g_scores[NB * NP];
__device__ int    g_labels[NB * NP];
__device__ float4 g_boxes[NB * NP];
__device__ int    g_valid[NB * NP];

// ---------------- Kernel A: softmax-max/argmax + decode + clip ----------------
// One warp per proposal. Lanes cover classes {lane, lane+32, lane+64}.
__global__ void score_decode_kernel(const float* __restrict__ logits,
                                    const float* __restrict__ deltas,
                                    const float* __restrict__ props,
                                    const int*   __restrict__ imsz) {
    int gw   = (blockIdx.x * blockDim.x + threadIdx.x) >> 5;
    int lane = threadIdx.x & 31;
    if (gw >= NB * NP) return;

    const float* row = logits + (size_t)gw * NC;
    float l0 = row[lane];
    float l1 = row[lane + 32];
    bool  has2 = (lane < NC - 64);           // lane < 27
    float l2 = has2 ? row[lane + 64] : -FLT_MAX;

    // local argmax with first-index tie break
    float bv = l0; int bi = lane;
    if (l1 > bv) { bv = l1; bi = lane + 32; }
    if (l2 > bv) { bv = l2; bi = lane + 64; }
    // warp reduce (max value, min index on tie)
    #pragma unroll
    for (int o = 16; o; o >>= 1) {
        float ov = __shfl_down_sync(0xffffffffu, bv, o);
        int   oi = __shfl_down_sync(0xffffffffu, bi, o);
        if (ov > bv || (ov == bv && oi < bi)) { bv = ov; bi = oi; }
    }
    bv = __shfl_sync(0xffffffffu, bv, 0);
    bi = __shfl_sync(0xffffffffu, bi, 0);

    float s = expf(l0 - bv) + expf(l1 - bv) + (has2 ? expf(l2 - bv) : 0.0f);
    #pragma unroll
    for (int o = 16; o; o >>= 1) s += __shfl_down_sync(0xffffffffu, s, o);

    if (lane == 0) {
        float score = 1.0f / s;
        int label = bi;
        int b = gw / NP;
        int valid = (label > 0) && (score > SCORE_THRESH);

        const float* p = props + (size_t)gw * 4;
        float x1 = p[0], y1 = p[1], x2 = p[2], y2 = p[3];
        float w = x2 - x1, h = y2 - y1;
        float cx = x1 + 0.5f * w, cy = y1 + 0.5f * h;

        const float* dd = deltas + (size_t)gw * (NC * 4) + 4 * label;
        float dx = dd[0], dy = dd[1];
        float dw = fminf(dd[2], BBOX_CLIP), dh = fminf(dd[3], BBOX_CLIP);
        float pcx = dx * w + cx, pcy = dy * h + cy;
        float pw = expf(dw) * w, ph = expf(dh) * h;
        float bx1 = pcx - 0.5f * pw, by1 = pcy - 0.5f * ph;
        float bx2 = pcx + 0.5f * pw, by2 = pcy + 0.5f * ph;

        float hb = (float)imsz[b * 2 + 0];
        float wb = (float)imsz[b * 2 + 1];
        bx1 = fminf(fmaxf(bx1, 0.0f), wb);
        by1 = fminf(fmaxf(by1, 0.0f), hb);
        bx2 = fminf(fmaxf(bx2, 0.0f), wb);
        by2 = fminf(fmaxf(by2, 0.0f), hb);

        g_boxes[gw]  = make_float4(bx1, by1, bx2, by2);
        g_scores[gw] = score;
        g_labels[gw] = label;
        g_valid[gw]  = valid;
    }
}

// ---------------- hybrid bitonic helpers ----------------
__device__ __forceinline__ unsigned long long cswap_shfl(unsigned long long key,
                                                         int t, int j, int k) {
    unsigned long long other = __shfl_xor_sync(0xffffffffu, key, j);
    bool up      = ((t & k) == 0);
    bool lower   = ((t & j) == 0);
    bool keepmin = (lower == up);
    unsigned long long mn = key < other ? key : other;
    unsigned long long mx = key < other ? other : key;
    return keepmin ? mn : mx;
}

// Full ascending bitonic sort of s_key[0..1023]; 1024 threads, keys start in smem
// (caller must have a __syncthreads() after writing s_key). Ends with keys in smem
// and a trailing __syncthreads().
__device__ __forceinline__ void bitonic_sort_1024(unsigned long long* s_key, int t) {
    // stages k = 2..32 entirely in registers (partner within warp)
    unsigned long long key = s_key[t];
    #pragma unroll
    for (int k = 2; k <= 32; k <<= 1) {
        #pragma unroll
        for (int j = k >> 1; j >= 1; j >>= 1) {
            key = cswap_shfl(key, t, j, k);
        }
    }
    s_key[t] = key;
    __syncthreads();

    // stages k = 64..1024: smem steps for j>=32, register tail for j<=16
    for (int k = 64; k <= 1024; k <<= 1) {
        for (int j = k >> 1; j >= 32; j >>= 1) {
            if ((t & j) == 0) {
                unsigned long long a = s_key[t];
                unsigned long long c = s_key[t ^ j];
                bool up = ((t & k) == 0);
                if ((a > c) == up) { s_key[t] = c; s_key[t ^ j] = a; }
            }
            __syncthreads();
        }
        key = s_key[t];
        #pragma unroll
        for (int j = 16; j >= 1; j >>= 1) {
            key = cswap_shfl(key, t, j, k);
        }
        s_key[t] = key;
        __syncthreads();
    }
}

// ---------------- Kernel B: per-image sort + per-class NMS + top-100 ----------------
// One CTA (1024 threads) per image.
__global__ __launch_bounds__(1024) void nms_kernel(float* __restrict__ out) {
    const int b = blockIdx.x;
    const int t = threadIdx.x;

    __shared__ unsigned long long s_key[NP];   // 8 KB
    __shared__ float4 s_obox[NP];              // 16 KB (offset boxes, sorted order)
    __shared__ int    s_kept[NP];              // 4 KB
    __shared__ float  s_wmax[32];
    __shared__ float  s_K;

    const int g = b * NP + t;
    float  score = g_scores[g];
    int    label = g_labels[g];
    int    valid = g_valid[g];
    float4 bx    = g_boxes[g];

    // max_coord over valid boxes (invalid contribute 0, like the reference)
    {
        float mc = valid ? fmaxf(fmaxf(bx.x, bx.y), fmaxf(bx.z, bx.w)) : 0.0f;
        #pragma unroll
        for (int o = 16; o; o >>= 1)
            mc = fmaxf(mc, __shfl_xor_sync(0xffffffffu, mc, o));
        if ((t & 31) == 0) s_wmax[t >> 5] = mc;
        __syncthreads();
        if (t < 32) {
            float v = s_wmax[t];
            #pragma unroll
            for (int o = 16; o; o >>= 1)
                v = fmaxf(v, __shfl_xor_sync(0xffffffffu, v, o));
            if (t == 0) s_K = v + 1.0f;
        }
    }

    // key: [label:7][~score_bits:32][idx:10]  (ascending = label asc, score desc, idx asc)
    unsigned int ds = ~__float_as_uint(score);   // scores > 0, monotone in uint bits
    unsigned long long k = valid
        ? (((unsigned long long)label << 42) |
           ((unsigned long long)ds << 10) |
           (unsigned long long)(unsigned)t)
        : ~0ULL;
    s_key[t] = k;
    __syncthreads();

    bitonic_sort_1024(s_key, t);

    // offset boxes in sorted order + kept init
    {
        unsigned long long kt = s_key[t];
        if (kt != ~0ULL) {
            int oi = (int)(kt & 1023ULL);
            int lb = (int)(kt >> 42);
            float off = (float)lb * s_K;         // matches labels*(max_coord+1.0)
            float4 v = g_boxes[b * NP + oi];
            s_obox[t] = make_float4(v.x + off, v.y + off, v.z + off, v.w + off);
            s_kept[t] = 1;
        } else {
            s_kept[t] = 0;
        }
    }
    __syncthreads();

    // per-class greedy NMS, one warp per class (classes 1..90)
    {
        int warp = t >> 5, lane = t & 31;
        for (int c = 1 + warp; c <= 90; c += 32) {
            int lo = 0, hi = 0;
            if (lane == 0) {
                int l = 0, r = NP;
                while (l < r) { int m = (l + r) >> 1; if ((int)(s_key[m] >> 42) < c) l = m + 1; else r = m; }
                lo = l;
                r = NP;
                while (l < r) { int m = (l + r) >> 1; if ((int)(s_key[m] >> 42) < c + 1) l = m + 1; else r = m; }
                hi = l;
            }
            lo = __shfl_sync(0xffffffffu, lo, 0);
            hi = __shfl_sync(0xffffffffu, hi, 0);
            for (int a = lo; a < hi - 1; ++a) {
                if (s_kept[a]) {
                    float4 A = s_obox[a];
                    float areaA = (A.z - A.x) * (A.w - A.y);
                    for (int bb = a + 1 + lane; bb < hi; bb += 32) {
                        if (s_kept[bb]) {
                            float4 Bx = s_obox[bb];
                            float areaB = (Bx.z - Bx.x) * (Bx.w - Bx.y);
                            float ltx = fmaxf(A.x, Bx.x), lty = fmaxf(A.y, Bx.y);
                            float rbx = fminf(A.z, Bx.z), rby = fminf(A.w, Bx.w);
                            float wx = fmaxf(rbx - ltx, 0.0f), wy = fmaxf(rby - lty, 0.0f);
                            float inter = wx * wy;
                            float uni = areaA + areaB - inter;
                            float iou = inter / (uni + 1e-9f);
                            if (iou > NMS_THRESH) s_kept[bb] = 0;
                        }
                    }
                }
                __syncwarp();
            }
        }
    }
    __syncthreads();

    // second key: kept entries by (score desc, idx asc); others to the end
    unsigned long long k2 = (s_kept[t] && s_key[t] != ~0ULL)
        ? (s_key[t] & ((1ULL << 42) - 1ULL))
        : ~0ULL;
    __syncthreads();
    s_key[t] = k2;
    __syncthreads();

    bitonic_sort_1024(s_key, t);

    // output: boxes [NB,100,4] | scores [NB,100] | labels [NB,100]  (all f32)
    if (t < MAX_DET) {
        float* boxes_out  = out;
        float* scores_out = out + NB * MAX_DET * 4;
        float* labels_out = out + NB * MAX_DET * 5;
        unsigned long long kt = s_key[t];
        int base = b * MAX_DET + t;
        if (kt != ~0ULL) {
            int oi = (int)(kt & 1023ULL);
            float4 v = g_boxes[b * NP + oi];
            boxes_out[base * 4 + 0] = v.x;
            boxes_out[base * 4 + 1] = v.y;
            boxes_out[base * 4 + 2] = v.z;
            boxes_out[base * 4 + 3] = v.w;
            scores_out[base] = g_scores[b * NP + oi];
            labels_out[base] = (float)g_labels[b * NP + oi];
        } else {
            boxes_out[base * 4 + 0] = 0.0f;
            boxes_out[base * 4 + 1] = 0.0f;
            boxes_out[base * 4 + 2] = 0.0f;
            boxes_out[base * 4 + 3] = 0.0f;
            scores_out[base] = 0.0f;
            labels_out[base] = -1.0f;
        }
    }
}

// ---------------- launch ----------------
extern "C" void kernel_launch(void* const* d_in, const int* in_sizes, int n_in,
                              void* d_out, int out_size) {
    const float* class_logits  = (const float*)d_in[0];
    const float* bbox_deltas   = (const float*)d_in[1];
    const float* roi_proposals = (const float*)d_in[2];
    const int*   image_sizes   = (const int*)d_in[3];
    float* out = (float*)d_out;

    // Kernel A: 16384 warps, 8 warps/block
    int total_warps = NB * NP;
    int threads = 256;
    int blocks = (total_warps * 32 + threads - 1) / threads;
    score_decode_kernel<<<blocks, threads>>>(class_logits, bbox_deltas,
                                             roi_proposals, image_sizes);

    // Kernel B: one CTA per image
    nms_kernel<<<NB, 1024>>>(out);
}